// round 2
// baseline (speedup 1.0000x reference)
#include <cuda_runtime.h>
#include <math.h>

#define Bn 4
#define Hn 8
#define Nn 4096
#define Dn 64
#define Mn 256
#define NHEAD (Bn*Hn)

// ---- scratch (device globals: no allocation allowed in kernel_launch) ----
static __device__ float        g_KP[(size_t)NHEAD*Nn*Mn];   // 134 MB projected-K
static __device__ float        g_diag[NHEAD*Nn];
static __device__ unsigned int g_stab[NHEAD];
static __device__ float        g_ctx[NHEAD*Mn*Dn];
static __device__ float        g_ksum[NHEAD*Mn];

__device__ __forceinline__ unsigned f2ord(float f){
    unsigned u = __float_as_uint(f);
    return (u & 0x80000000u) ? ~u : (u | 0x80000000u);
}
__device__ __forceinline__ float ord2f(unsigned u){
    return __uint_as_float((u & 0x80000000u) ? (u ^ 0x80000000u) : ~u);
}

__global__ void k_init(){
    int idx = blockIdx.x*blockDim.x + threadIdx.x;
    if (idx < NHEAD*Mn*Dn) g_ctx[idx]  = 0.f;
    if (idx < NHEAD*Mn)    g_ksum[idx] = 0.f;
    if (idx < NHEAD)       g_stab[idx] = 0u;
}

// ---------------------------------------------------------------------------
// Kernel A: KP = (K*scale*mask) @ proj^T  per head; also diag_k and global max
// grid (Nn/64, NHEAD), 256 threads. smem: sK[64][65] + sPt[64][256]
// ---------------------------------------------------------------------------
__global__ __launch_bounds__(256) void k_projK(const float* __restrict__ Kp,
                                               const float* __restrict__ mask,
                                               const float* __restrict__ proj){
    extern __shared__ float sm[];
    float* sK  = sm;           // 64 x 65 (padded)
    float* sPt = sm + 64*65;   // [d][m] transposed projection
    __shared__ float sred[8];

    const int head = blockIdx.y;
    const int bIdx = head / Hn;
    const int n0   = blockIdx.x * 64;
    const int tid  = threadIdx.x;
    const float scale = 0.35355339059327373f;   // 64^-0.25

    for (int i = tid; i < 64*64; i += 256){
        int r = i >> 6, d = i & 63;
        float mv = mask[bIdx*Nn + n0 + r];
        sK[r*65 + d] = Kp[((size_t)head*Nn + n0 + r)*Dn + d] * (scale*mv);
    }
    for (int i = tid; i < Mn*16; i += 256){
        int m = i >> 4, dq = i & 15;
        float4 p = reinterpret_cast<const float4*>(proj)[m*16 + dq];
        sPt[(dq*4+0)*Mn + m] = p.x;
        sPt[(dq*4+1)*Mn + m] = p.y;
        sPt[(dq*4+2)*Mn + m] = p.z;
        sPt[(dq*4+3)*Mn + m] = p.w;
    }
    __syncthreads();

    const int mt = tid & 31, nt = tid >> 5;
    float acc[8][8];
    #pragma unroll
    for (int i=0;i<8;i++)
        #pragma unroll
        for (int j=0;j<8;j++) acc[i][j] = 0.f;

    #pragma unroll 4
    for (int d = 0; d < 64; d++){
        float a[8], bb[8];
        #pragma unroll
        for (int i=0;i<8;i++) a[i]  = sK[(nt+8*i)*65 + d];
        #pragma unroll
        for (int j=0;j<8;j++) bb[j] = sPt[d*Mn + mt + 32*j];
        #pragma unroll
        for (int i=0;i<8;i++)
            #pragma unroll
            for (int j=0;j<8;j++) acc[i][j] = fmaf(a[i], bb[j], acc[i][j]);
    }

    float lmax = -3.4e38f;
    #pragma unroll
    for (int i=0;i<8;i++){
        size_t base = ((size_t)head*Nn + n0 + nt + 8*i)*Mn + mt;
        #pragma unroll
        for (int j=0;j<8;j++){
            g_KP[base + 32*j] = acc[i][j];
            lmax = fmaxf(lmax, acc[i][j]);
        }
    }
    #pragma unroll
    for (int off=16; off>0; off>>=1)
        lmax = fmaxf(lmax, __shfl_xor_sync(0xffffffffu, lmax, off));
    if (mt == 0) sred[nt] = lmax;
    __syncthreads();

    if (tid < 64){
        float s = 0.f;
        #pragma unroll 8
        for (int d=0; d<64; d++){ float v = sK[tid*65 + d]; s = fmaf(v, v, s); }
        g_diag[head*Nn + n0 + tid] = 0.5f*s;
    }
    if (tid == 0){
        float m2 = sred[0];
        #pragma unroll
        for (int w=1; w<8; w++) m2 = fmaxf(m2, sred[w]);
        atomicMax(&g_stab[head], f2ord(m2));
    }
}

// ---------------------------------------------------------------------------
// Kernel C: phi_k = ratio*(exp(KP - diag - stab)+eps);
//           ksum += sum_n phi_k; ctx[m][e] += sum_n phi_k[n][m]*v[n][e]
// grid (8 splits, NHEAD), 256 threads.
// ---------------------------------------------------------------------------
__global__ __launch_bounds__(256) void k_ctx(const float* __restrict__ V,
                                             const float* __restrict__ mask){
    extern __shared__ float sm[];
    float* sPhi  = sm;              // 16 x 256
    float* sV    = sm + 16*256;     // 16 x 64
    float* sDiag = sV + 16*64;      // 16

    const int head  = blockIdx.y;
    const int bIdx  = head / Hn;
    const int nbase0= blockIdx.x * (Nn/8);
    const int tid   = threadIdx.x;
    const float stab = ord2f(g_stab[head]);
    const float ratio = 0.0625f, eps = 1e-4f;
    const int mgrp = tid & 31, egrp = tid >> 5;

    float acc[8][8];
    #pragma unroll
    for (int j=0;j<8;j++)
        #pragma unroll
        for (int t=0;t<8;t++) acc[j][t] = 0.f;
    float ak = 0.f;

    for (int nb = nbase0; nb < nbase0 + Nn/8; nb += 16){
        if (tid < 16) sDiag[tid] = g_diag[head*Nn + nb + tid];
        for (int i = tid; i < 16*64; i += 256){
            int r = i >> 6;
            sV[i] = V[((size_t)head*Nn + nb + r)*Dn + (i & 63)]
                  * mask[bIdx*Nn + nb + r];
        }
        __syncthreads();

        const float* kpBase = &g_KP[((size_t)head*Nn + nb)*Mn + tid];
        #pragma unroll
        for (int s=0; s<16; s++){
            float xp = kpBase[(size_t)s*Mn];
            float ph = ratio*(__expf(xp - sDiag[s] - stab) + eps);
            sPhi[s*256 + tid] = ph;
            ak += ph;
        }
        __syncthreads();

        #pragma unroll 2
        for (int s=0; s<16; s++){
            float a[8], bv[8];
            #pragma unroll
            for (int j=0;j<8;j++) a[j]  = sPhi[s*256 + mgrp + 32*j];
            #pragma unroll
            for (int t=0;t<8;t++) bv[t] = sV[s*64 + egrp + 8*t];
            #pragma unroll
            for (int j=0;j<8;j++)
                #pragma unroll
                for (int t=0;t<8;t++) acc[j][t] = fmaf(a[j], bv[t], acc[j][t]);
        }
        __syncthreads();
    }

    atomicAdd(&g_ksum[head*Mn + tid], ak);
    #pragma unroll
    for (int j=0;j<8;j++){
        size_t base = ((size_t)head*Mn + mgrp + 32*j)*Dn + egrp;
        #pragma unroll
        for (int t=0;t<8;t++) atomicAdd(&g_ctx[base + 8*t], acc[j][t]);
    }
}

// ---------------------------------------------------------------------------
// Kernel D: QP GEMM -> rowmax -> phi_q -> D_inv -> out = phi_q @ ctx * D_inv
// grid (Nn/64, NHEAD), 256 threads.
// ---------------------------------------------------------------------------
__global__ __launch_bounds__(256) void k_out(const float* __restrict__ Qp,
                                             const float* __restrict__ proj,
                                             float* __restrict__ outp){
    extern __shared__ float sm[];
    float* sQ   = sm;                 // 64 x 65
    float* sB   = sQ + 64*65;         // 64 x 256 (proj^T, then ctx[m][e])
    float* sPhi = sB + 64*256;        // 64 x 256
    float* sKs  = sPhi + 64*256;      // 256
    __shared__ float sDg[64];

    const int head = blockIdx.y;
    const int n0   = blockIdx.x * 64;
    const int tid  = threadIdx.x;
    const float scale = 0.35355339059327373f;
    const float ratio = 0.0625f, eps = 1e-4f;

    sKs[tid] = g_ksum[head*Mn + tid];
    for (int i = tid; i < 64*64; i += 256){
        int r = i >> 6, d = i & 63;
        sQ[r*65 + d] = Qp[((size_t)head*Nn + n0 + r)*Dn + d] * scale;
    }
    for (int i = tid; i < Mn*16; i += 256){
        int m = i >> 4, dq = i & 15;
        float4 p = reinterpret_cast<const float4*>(proj)[m*16 + dq];
        sB[(dq*4+0)*Mn + m] = p.x;
        sB[(dq*4+1)*Mn + m] = p.y;
        sB[(dq*4+2)*Mn + m] = p.z;
        sB[(dq*4+3)*Mn + m] = p.w;
    }
    __syncthreads();
    if (tid < 64){
        float s = 0.f;
        #pragma unroll 8
        for (int d=0; d<64; d++){ float v = sQ[tid*65 + d]; s = fmaf(v, v, s); }
        sDg[tid] = 0.5f*s;
    }
    __syncthreads();

    const int mt = tid & 31, nt = tid >> 5;
    float acc[8][8];
    #pragma unroll
    for (int i=0;i<8;i++)
        #pragma unroll
        for (int j=0;j<8;j++) acc[i][j] = 0.f;

    #pragma unroll 4
    for (int d = 0; d < 64; d++){
        float a[8], bb[8];
        #pragma unroll
        for (int i=0;i<8;i++) a[i]  = sQ[(nt+8*i)*65 + d];
        #pragma unroll
        for (int j=0;j<8;j++) bb[j] = sB[d*Mn + mt + 32*j];
        #pragma unroll
        for (int i=0;i<8;i++)
            #pragma unroll
            for (int j=0;j<8;j++) acc[i][j] = fmaf(a[i], bb[j], acc[i][j]);
    }

    // per-row max (warp owns rows nt+8i; mt spans the 32 m-lanes), phi, D
    float Dinv[8];
    #pragma unroll
    for (int i=0;i<8;i++){
        float rm = acc[i][0];
        #pragma unroll
        for (int j=1;j<8;j++) rm = fmaxf(rm, acc[i][j]);
        #pragma unroll
        for (int off=16; off>0; off>>=1)
            rm = fmaxf(rm, __shfl_xor_sync(0xffffffffu, rm, off));
        float dg = sDg[nt + 8*i];
        float ds = 0.f;
        #pragma unroll
        for (int j=0;j<8;j++){
            float ph = ratio*(__expf(acc[i][j] - dg - rm) + eps);
            ds = fmaf(ph, sKs[mt + 32*j], ds);
            sPhi[(nt+8*i)*Mn + mt + 32*j] = ph;
        }
        #pragma unroll
        for (int off=16; off>0; off>>=1)
            ds += __shfl_xor_sync(0xffffffffu, ds, off);
        Dinv[i] = 1.f/ds;
    }
    __syncthreads();

    // swap proj -> ctx in sB
    for (int i = tid; i < Mn*Dn; i += 256) sB[i] = g_ctx[(size_t)head*Mn*Dn + i];
    __syncthreads();

    const int et = mt;
    float acc2[8][2];
    #pragma unroll
    for (int i=0;i<8;i++){ acc2[i][0]=0.f; acc2[i][1]=0.f; }

    #pragma unroll 8
    for (int m = 0; m < Mn; m++){
        float b0 = sB[m*Dn + et], b1 = sB[m*Dn + et + 32];
        #pragma unroll
        for (int i=0;i<8;i++){
            float a = sPhi[(nt+8*i)*Mn + m];
            acc2[i][0] = fmaf(a, b0, acc2[i][0]);
            acc2[i][1] = fmaf(a, b1, acc2[i][1]);
        }
    }
    #pragma unroll
    for (int i=0;i<8;i++){
        size_t base = ((size_t)head*Nn + n0 + nt + 8*i)*Dn + et;
        outp[base]      = acc2[i][0]*Dinv[i];
        outp[base + 32] = acc2[i][1]*Dinv[i];
    }
}

// ---------------------------------------------------------------------------
extern "C" void kernel_launch(void* const* d_in, const int* in_sizes, int n_in,
                              void* d_out, int out_size) {
    const float* Q    = (const float*)d_in[0];
    const float* K    = (const float*)d_in[1];
    const float* V    = (const float*)d_in[2];
    const float* mask = (const float*)d_in[3];
    const float* proj = (const float*)d_in[4];
    float* out        = (float*)d_out;

    const int smA = (64*65 + 64*256) * 4;                     // 82176
    const int smC = (16*256 + 16*64 + 16) * 4;                // 20544
    const int smD = (64*65 + 64*256 + 64*256 + 256) * 4;      // 148736

    cudaFuncSetAttribute(k_projK, cudaFuncAttributeMaxDynamicSharedMemorySize, smA);
    cudaFuncSetAttribute(k_out,   cudaFuncAttributeMaxDynamicSharedMemorySize, smD);

    k_init<<<(NHEAD*Mn*Dn + 255)/256, 256>>>();
    k_projK<<<dim3(Nn/64, NHEAD), 256, smA>>>(K, mask, proj);
    k_ctx  <<<dim3(8,     NHEAD), 256, smC>>>(V, mask);
    k_out  <<<dim3(Nn/64, NHEAD), 256, smD>>>(Q, proj, out);
}

// round 5
// speedup vs baseline: 1.1663x; 1.1663x over previous
#include <cuda_runtime.h>
#include <math.h>

#define Bn 4
#define Hn 8
#define Nn 4096
#define Dn 64
#define Mn 256
#define NHEAD (Bn*Hn)

// ---- scratch (device globals: no allocation allowed in kernel_launch) ----
static __device__ float        g_KP[(size_t)NHEAD*Nn*Mn];   // 134 MB projected-K
static __device__ float        g_QP[(size_t)NHEAD*Nn*Mn];   // 134 MB phi_q * Dinv
static __device__ float        g_diag[NHEAD*Nn];
static __device__ unsigned int g_stab[NHEAD];
static __device__ float        g_ctx[NHEAD*Mn*Dn];
static __device__ float        g_ksum[NHEAD*Mn];

typedef unsigned long long ull;

__device__ __forceinline__ ull pk2(float x){
    ull r;
    asm("mov.b64 %0, {%1, %1};" : "=l"(r) : "r"(__float_as_uint(x)));
    return r;
}
__device__ __forceinline__ void fma2(ull &c, ull a, ull b){
    asm("fma.rn.f32x2 %0, %1, %2, %0;" : "+l"(c) : "l"(a), "l"(b));
}
__device__ __forceinline__ float2 up2(ull v){
    unsigned lo, hi;
    asm("mov.b64 {%0, %1}, %2;" : "=r"(lo), "=r"(hi) : "l"(v));
    return make_float2(__uint_as_float(lo), __uint_as_float(hi));
}

__device__ __forceinline__ unsigned f2ord(float f){
    unsigned u = __float_as_uint(f);
    return (u & 0x80000000u) ? ~u : (u | 0x80000000u);
}
__device__ __forceinline__ float ord2f(unsigned u){
    return __uint_as_float((u & 0x80000000u) ? (u ^ 0x80000000u) : ~u);
}

__global__ void k_init(){
    int idx = blockIdx.x*blockDim.x + threadIdx.x;
    if (idx < NHEAD*Mn*Dn) g_ctx[idx]  = 0.f;
    if (idx < NHEAD*Mn)    g_ksum[idx] = 0.f;
    if (idx < NHEAD)       g_stab[idx] = 0u;
}

// ---------------------------------------------------------------------------
// Kernel A: KP = (K*scale*mask) @ proj^T  per head; also diag_k and global max
// grid (Nn/64, NHEAD), 256 threads. smem: sK[64][65] + sPt[64][256]
// f32x2 micro-kernel: 8 rows x 8 m (4 m-pairs) per thread.
// ---------------------------------------------------------------------------
__global__ __launch_bounds__(256,2) void k_projK(const float* __restrict__ Kp,
                                                 const float* __restrict__ mask,
                                                 const float* __restrict__ proj){
    extern __shared__ float sm[];
    float* sK  = sm;           // 64 x 65 (padded)
    float* sPt = sm + 64*65;   // [d][m] transposed projection
    __shared__ float sred[8];

    const int head = blockIdx.y;
    const int bIdx = head / Hn;
    const int n0   = blockIdx.x * 64;
    const int tid  = threadIdx.x;
    const float scale = 0.35355339059327373f;   // 64^-0.25

    for (int i = tid; i < 64*64; i += 256){
        int r = i >> 6, d = i & 63;
        float mv = mask[bIdx*Nn + n0 + r];
        sK[r*65 + d] = Kp[((size_t)head*Nn + n0 + r)*Dn + d] * (scale*mv);
    }
    for (int i = tid; i < Mn*16; i += 256){
        int m = i >> 4, dq = i & 15;
        float4 p = reinterpret_cast<const float4*>(proj)[m*16 + dq];
        sPt[(dq*4+0)*Mn + m] = p.x;
        sPt[(dq*4+1)*Mn + m] = p.y;
        sPt[(dq*4+2)*Mn + m] = p.z;
        sPt[(dq*4+3)*Mn + m] = p.w;
    }
    __syncthreads();

    const int mt = tid & 31, nt = tid >> 5;
    ull acc[8][4];
    #pragma unroll
    for (int i=0;i<8;i++)
        #pragma unroll
        for (int j=0;j<4;j++) acc[i][j] = 0ull;

    #pragma unroll 4
    for (int d = 0; d < 64; d++){
        ull a2[8], b2[4];
        #pragma unroll
        for (int i=0;i<8;i++) a2[i] = pk2(sK[(nt+8*i)*65 + d]);
        #pragma unroll
        for (int j=0;j<4;j++) b2[j] = *reinterpret_cast<const ull*>(&sPt[d*Mn + 64*j + 2*mt]);
        #pragma unroll
        for (int i=0;i<8;i++)
            #pragma unroll
            for (int j=0;j<4;j++) fma2(acc[i][j], a2[i], b2[j]);
    }

    float lmax = -3.4e38f;
    #pragma unroll
    for (int i=0;i<8;i++){
        size_t base = ((size_t)head*Nn + n0 + nt + 8*i)*Mn + 2*mt;
        #pragma unroll
        for (int j=0;j<4;j++){
            float2 v = up2(acc[i][j]);
            *reinterpret_cast<float2*>(&g_KP[base + 64*j]) = v;
            lmax = fmaxf(lmax, fmaxf(v.x, v.y));
        }
    }
    #pragma unroll
    for (int off=16; off>0; off>>=1)
        lmax = fmaxf(lmax, __shfl_xor_sync(0xffffffffu, lmax, off));
    if (mt == 0) sred[nt] = lmax;
    __syncthreads();

    if (tid < 64){
        float s = 0.f;
        #pragma unroll 8
        for (int d=0; d<64; d++){ float v = sK[tid*65 + d]; s = fmaf(v, v, s); }
        g_diag[head*Nn + n0 + tid] = 0.5f*s;
    }
    if (tid == 0){
        float m2 = sred[0];
        #pragma unroll
        for (int w=1; w<8; w++) m2 = fmaxf(m2, sred[w]);
        atomicMax(&g_stab[head], f2ord(m2));
    }
}

// ---------------------------------------------------------------------------
// Kernel C: phi_k = ratio*(exp(KP - diag - stab)+eps);
//           ksum += sum_n phi_k; ctx[m][e] += sum_n phi_k[n][m]*v[n][e]
// grid (16 splits, NHEAD), 256 threads. f32x2: 8 m (4 pairs) x 8 e per thread.
// ---------------------------------------------------------------------------
#define NSPLIT 16
__global__ __launch_bounds__(256,2) void k_ctx(const float* __restrict__ V,
                                               const float* __restrict__ mask){
    extern __shared__ float sm[];
    float* sPhi  = sm;              // 16 x 256
    float* sV    = sm + 16*256;     // 16 x 64
    float* sDiag = sV + 16*64;      // 16

    const int head  = blockIdx.y;
    const int bIdx  = head / Hn;
    const int nbase0= blockIdx.x * (Nn/NSPLIT);
    const int tid   = threadIdx.x;
    const float stab = ord2f(g_stab[head]);
    const float ratio = 0.0625f, eps = 1e-4f;
    const int mgrp = tid & 31, egrp = tid >> 5;

    ull acc[4][8];
    #pragma unroll
    for (int j=0;j<4;j++)
        #pragma unroll
        for (int t=0;t<8;t++) acc[j][t] = 0ull;
    float ak = 0.f;

    for (int nb = nbase0; nb < nbase0 + Nn/NSPLIT; nb += 16){
        if (tid < 16) sDiag[tid] = g_diag[head*Nn + nb + tid];
        for (int i = tid; i < 16*64; i += 256){
            int r = i >> 6;
            sV[i] = V[((size_t)head*Nn + nb + r)*Dn + (i & 63)]
                  * mask[bIdx*Nn + nb + r];
        }
        __syncthreads();

        const float* kpBase = &g_KP[((size_t)head*Nn + nb)*Mn + tid];
        #pragma unroll
        for (int s=0; s<16; s++){
            float xp = kpBase[(size_t)s*Mn];
            float ph = ratio*(__expf(xp - sDiag[s] - stab) + eps);
            sPhi[s*256 + tid] = ph;
            ak += ph;
        }
        __syncthreads();

        #pragma unroll 2
        for (int s=0; s<16; s++){
            ull a2[4], b2[8];
            #pragma unroll
            for (int j=0;j<4;j++)
                a2[j] = *reinterpret_cast<const ull*>(&sPhi[s*256 + 2*mgrp + 64*j]);
            #pragma unroll
            for (int t=0;t<8;t++) b2[t] = pk2(sV[s*64 + 8*egrp + t]);
            #pragma unroll
            for (int j=0;j<4;j++)
                #pragma unroll
                for (int t=0;t<8;t++) fma2(acc[j][t], a2[j], b2[t]);
        }
        __syncthreads();
    }

    atomicAdd(&g_ksum[head*Mn + tid], ak);
    #pragma unroll
    for (int j=0;j<4;j++){
        int m0 = 2*mgrp + 64*j;
        #pragma unroll
        for (int t=0;t<8;t++){
            float2 v = up2(acc[j][t]);
            atomicAdd(&g_ctx[((size_t)head*Mn + m0    )*Dn + 8*egrp + t], v.x);
            atomicAdd(&g_ctx[((size_t)head*Mn + m0 + 1)*Dn + 8*egrp + t], v.y);
        }
    }
}

// ---------------------------------------------------------------------------
// Kernel Q: QP GEMM -> rowmax -> phi_q -> D_inv -> store phi_q*D_inv to g_QP
// grid (Nn/64, NHEAD), 256 threads. smem: sQ[64][65] + sPt[64][256] + sKs[256]
// ---------------------------------------------------------------------------
__global__ __launch_bounds__(256,2) void k_qphi(const float* __restrict__ Qp,
                                                const float* __restrict__ proj){
    extern __shared__ float sm[];
    float* sQ  = sm;                 // 64 x 65
    float* sPt = sQ + 64*65;         // 64 x 256
    float* sKs = sPt + 64*256;       // 256
    __shared__ float sDg[64];

    const int head = blockIdx.y;
    const int n0   = blockIdx.x * 64;
    const int tid  = threadIdx.x;
    const float scale = 0.35355339059327373f;
    const float ratio = 0.0625f, eps = 1e-4f;

    sKs[tid] = g_ksum[head*Mn + tid];
    for (int i = tid; i < 64*64; i += 256){
        int r = i >> 6, d = i & 63;
        sQ[r*65 + d] = Qp[((size_t)head*Nn + n0 + r)*Dn + d] * scale;
    }
    for (int i = tid; i < Mn*16; i += 256){
        int m = i >> 4, dq = i & 15;
        float4 p = reinterpret_cast<const float4*>(proj)[m*16 + dq];
        sPt[(dq*4+0)*Mn + m] = p.x;
        sPt[(dq*4+1)*Mn + m] = p.y;
        sPt[(dq*4+2)*Mn + m] = p.z;
        sPt[(dq*4+3)*Mn + m] = p.w;
    }
    __syncthreads();
    if (tid < 64){
        float s = 0.f;
        #pragma unroll 8
        for (int d=0; d<64; d++){ float v = sQ[tid*65 + d]; s = fmaf(v, v, s); }
        sDg[tid] = 0.5f*s;
    }
    __syncthreads();

    const int mt = tid & 31, nt = tid >> 5;
    ull acc[8][4];
    #pragma unroll
    for (int i=0;i<8;i++)
        #pragma unroll
        for (int j=0;j<4;j++) acc[i][j] = 0ull;

    #pragma unroll 4
    for (int d = 0; d < 64; d++){
        ull a2[8], b2[4];
        #pragma unroll
        for (int i=0;i<8;i++) a2[i] = pk2(sQ[(nt+8*i)*65 + d]);
        #pragma unroll
        for (int j=0;j<4;j++) b2[j] = *reinterpret_cast<const ull*>(&sPt[d*Mn + 64*j + 2*mt]);
        #pragma unroll
        for (int i=0;i<8;i++)
            #pragma unroll
            for (int j=0;j<4;j++) fma2(acc[i][j], a2[i], b2[j]);
    }

    // per row: rowmax over all 256 m (intra-thread 8 + shfl over lanes), phi, D
    #pragma unroll
    for (int i=0;i<8;i++){
        float x[8];
        #pragma unroll
        for (int j=0;j<4;j++){
            float2 v = up2(acc[i][j]);
            x[2*j] = v.x; x[2*j+1] = v.y;
        }
        float rm = x[0];
        #pragma unroll
        for (int j=1;j<8;j++) rm = fmaxf(rm, x[j]);
        #pragma unroll
        for (int off=16; off>0; off>>=1)
            rm = fmaxf(rm, __shfl_xor_sync(0xffffffffu, rm, off));
        float dg = sDg[nt + 8*i];
        float ds = 0.f;
        float ph[8];
        #pragma unroll
        for (int j=0;j<4;j++){
            int m0 = 64*j + 2*mt;
            ph[2*j]   = ratio*(__expf(x[2*j]   - dg - rm) + eps);
            ph[2*j+1] = ratio*(__expf(x[2*j+1] - dg - rm) + eps);
            ds = fmaf(ph[2*j],   sKs[m0],   ds);
            ds = fmaf(ph[2*j+1], sKs[m0+1], ds);
        }
        #pragma unroll
        for (int off=16; off>0; off>>=1)
            ds += __shfl_xor_sync(0xffffffffu, ds, off);
        float Dinv = 1.f/ds;
        size_t base = ((size_t)head*Nn + n0 + nt + 8*i)*Mn + 2*mt;
        #pragma unroll
        for (int j=0;j<4;j++){
            float2 v = make_float2(ph[2*j]*Dinv, ph[2*j+1]*Dinv);
            *reinterpret_cast<float2*>(&g_QP[base + 64*j]) = v;
        }
    }
}

// ---------------------------------------------------------------------------
// Kernel O: out = phiD @ ctx  ([256 rows x 64 e] tiles, K=256)
// grid (Nn/256, NHEAD), 256 threads. smem: sCtx[256][64] + sP[256][33]
// thread: 8 rows x 8 e (4 e-pairs)
// ---------------------------------------------------------------------------
__global__ __launch_bounds__(256,2) void k_out2(float* __restrict__ outp){
    extern __shared__ float sm[];
    float* sCtx = sm;            // 256 x 64
    float* sP   = sm + 256*64;   // 256 rows x 33 (chunk of 32 m)

    const int head = blockIdx.y;
    const int n0   = blockIdx.x * 256;
    const int tid  = threadIdx.x;
    const int rg = tid >> 3;     // 0..31 -> rows 8*rg..8*rg+7
    const int eg = tid & 7;      // 0..7  -> e 8*eg..8*eg+7

    for (int i = tid; i < Mn*Dn/4; i += 256)
        reinterpret_cast<float4*>(sCtx)[i] =
            reinterpret_cast<const float4*>(&g_ctx[(size_t)head*Mn*Dn])[i];

    ull acc[8][4];
    #pragma unroll
    for (int i=0;i<8;i++)
        #pragma unroll
        for (int u=0;u<4;u++) acc[i][u] = 0ull;

    for (int m0 = 0; m0 < Mn; m0 += 32){
        __syncthreads();
        // load phi chunk [256 rows][32 m]
        #pragma unroll
        for (int q = 0; q < 8; q++){
            int idx = tid + q*256;
            int r = idx >> 3, mq = idx & 7;
            float4 v = *reinterpret_cast<const float4*>(
                &g_QP[((size_t)head*Nn + n0 + r)*Mn + m0 + 4*mq]);
            float* dst = &sP[r*33 + 4*mq];
            dst[0]=v.x; dst[1]=v.y; dst[2]=v.z; dst[3]=v.w;
        }
        __syncthreads();

        #pragma unroll 4
        for (int m = 0; m < 32; m++){
            ull a2[8], b2[4];
            #pragma unroll
            for (int i=0;i<8;i++) a2[i] = pk2(sP[(8*rg+i)*33 + m]);
            const ull* cp = reinterpret_cast<const ull*>(&sCtx[(m0+m)*Dn + 8*eg]);
            #pragma unroll
            for (int u=0;u<4;u++) b2[u] = cp[u];
            #pragma unroll
            for (int i=0;i<8;i++)
                #pragma unroll
                for (int u=0;u<4;u++) fma2(acc[i][u], a2[i], b2[u]);
        }
    }

    #pragma unroll
    for (int i=0;i<8;i++){
        size_t base = ((size_t)head*Nn + n0 + 8*rg + i)*Dn + 8*eg;
        #pragma unroll
        for (int u=0;u<4;u++)
            *reinterpret_cast<float2*>(&outp[base + 2*u]) = up2(acc[i][u]);
    }
}

// ---------------------------------------------------------------------------
extern "C" void kernel_launch(void* const* d_in, const int* in_sizes, int n_in,
                              void* d_out, int out_size) {
    const float* Q    = (const float*)d_in[0];
    const float* K    = (const float*)d_in[1];
    const float* V    = (const float*)d_in[2];
    const float* mask = (const float*)d_in[3];
    const float* proj = (const float*)d_in[4];
    float* out        = (float*)d_out;

    const int smA = (64*65 + 64*256) * 4;            // 82176
    const int smC = (16*256 + 16*64 + 16) * 4;       // 20544
    const int smQ = (64*65 + 64*256 + 256) * 4;      // 83200
    const int smO = (256*64 + 256*33) * 4;           // 99328

    cudaFuncSetAttribute(k_projK, cudaFuncAttributeMaxDynamicSharedMemorySize, smA);
    cudaFuncSetAttribute(k_qphi,  cudaFuncAttributeMaxDynamicSharedMemorySize, smQ);
    cudaFuncSetAttribute(k_out2,  cudaFuncAttributeMaxDynamicSharedMemorySize, smO);

    k_init <<<(NHEAD*Mn*Dn + 255)/256, 256>>>();
    k_projK<<<dim3(Nn/64,  NHEAD), 256, smA>>>(K, mask, proj);
    k_ctx  <<<dim3(NSPLIT, NHEAD), 256, smC>>>(V, mask);
    k_qphi <<<dim3(Nn/64,  NHEAD), 256, smQ>>>(Q, proj);
    k_out2 <<<dim3(Nn/256, NHEAD), 256, smO>>>(out);
}